// round 15
// baseline (speedup 1.0000x reference)
#include <cuda_runtime.h>
#include <cuda_fp16.h>
#include <math.h>
#include <stdint.h>

#define BATCH 16
#define IMG 56
#define PP 28
#define NPOS 784
#define DIM 256
#define HEADS 8
#define DH 64
#define INNER 512

// ---------------- scratch (static device allocations; no cudaMalloc) -------
__device__ float  g_xpool[BATCH * NPOS * DIM];
__device__ float  g_attn2[BATCH * NPOS * 2];
__device__ float  g_q[BATCH * HEADS * NPOS * 2];
__device__ float  g_k[BATCH * HEADS * NPOS * 2];
__device__ __half g_vmid_h[BATCH * NPOS * DIM];
__device__ __half g_v_h[BATCH * NPOS * INNER];
__device__ __half g_ao_h[BATCH * NPOS * INNER];
__device__ __half g_y28_h[BATCH * NPOS * DIM];   // out-proj result (fp16)
__device__ __half g_pww_h[INNER * DIM];
__device__ __half g_oww_h[DIM * INNER];

__constant__ float c_W25[4] = {-0.10546875f, 0.87890625f, 0.26171875f, -0.03515625f};
__constant__ float c_W75[4] = {-0.03515625f, 0.26171875f, 0.87890625f, -0.10546875f};

// ---------------- helpers ---------------------------------------------------
__device__ __forceinline__ uint32_t pack_h2(float lo, float hi) {
    uint32_t r;
    asm("cvt.rn.f16x2.f32 %0, %1, %2;" : "=r"(r) : "f"(hi), "f"(lo));
    return r;
}
__device__ __forceinline__ uint32_t exp2_h2(float lo, float hi) {
    uint32_t s = pack_h2(lo, hi);
    uint32_t r;
    asm("ex2.approx.f16x2 %0, %1;" : "=r"(r) : "r"(s));
    return r;
}
__device__ __forceinline__ void mma_h(float c[4], uint32_t a0, uint32_t a1,
                                      uint32_t a2, uint32_t a3,
                                      uint32_t b0, uint32_t b1) {
    asm volatile(
        "mma.sync.aligned.m16n8k16.row.col.f32.f16.f16.f32 "
        "{%0,%1,%2,%3},{%4,%5,%6,%7},{%8,%9},{%0,%1,%2,%3};"
        : "+f"(c[0]), "+f"(c[1]), "+f"(c[2]), "+f"(c[3])
        : "r"(a0), "r"(a1), "r"(a2), "r"(a3), "r"(b0), "r"(b1));
}
__device__ __forceinline__ uint32_t smem_u32(const void* p) {
    uint32_t a;
    asm("{ .reg .u64 t; cvta.to.shared.u64 t, %1; cvt.u32.u64 %0, t; }" : "=r"(a) : "l"(p));
    return a;
}

// ---------------- 0) convert weights to fp16 once --------------------------
__global__ void round_weights_kernel(const float* __restrict__ pw,
                                     const float* __restrict__ ow) {
    int i = blockIdx.x * 256 + threadIdx.x;
    if (i < INNER * DIM) {
        g_pww_h[i] = __float2half(pw[i]);
        g_oww_h[i] = __float2half(ow[i]);
    }
}

// ---------------- 1) avgpool(3,2,1) + channel mean/max (px-split, 2ch) -----
__global__ void pool_part_kernel(const float* __restrict__ x) {
    __shared__ float srow[7][DIM];
    int quarter = blockIdx.x, py = blockIdx.y, b = blockIdx.z;
    int c2 = threadIdx.x, c = 2 * c2;
    int lane = c2 & 31, w4 = c2 >> 5;
    int px0 = quarter * 7;
    const float* base = x + (size_t)b * IMG * IMG * DIM + c;
    int rm = 2 * py - 1, r0 = 2 * py, rp = 2 * py + 1;
    bool vm = rm >= 0;

    float2 cs[15];
#pragma unroll
    for (int i = 0; i < 15; i++) {
        int ix = 2 * px0 - 1 + i;
        if ((unsigned)ix < IMG) {
            float2 a = *(const float2*)&base[(size_t)(r0 * IMG + ix) * DIM];
            float2 bq = *(const float2*)&base[(size_t)(rp * IMG + ix) * DIM];
            float2 v = make_float2(a.x + bq.x, a.y + bq.y);
            if (vm) {
                float2 m2 = *(const float2*)&base[(size_t)(rm * IMG + ix) * DIM];
                v.x += m2.x; v.y += m2.y;
            }
            cs[i] = v;
        } else cs[i] = make_float2(0.f, 0.f);
    }
    float* outp = g_xpool + ((size_t)b * NPOS + py * PP + px0) * DIM + c;
#pragma unroll
    for (int i = 0; i < 7; i++) {
        float2 pool;
        pool.x = (cs[2 * i].x + cs[2 * i + 1].x + cs[2 * i + 2].x) * (1.f / 9.f);
        pool.y = (cs[2 * i].y + cs[2 * i + 1].y + cs[2 * i + 2].y) * (1.f / 9.f);
        *(float2*)&outp[(size_t)i * DIM] = pool;
        *(float2*)&srow[i][c] = pool;
    }
    __syncthreads();
    for (int px = w4; px < 7; px += 4) {
        float s = 0.f, m = -1e30f;
#pragma unroll
        for (int k = 0; k < 8; k++) {
            float v = srow[px][lane + 32 * k];
            s += v; m = fmaxf(m, v);
        }
#pragma unroll
        for (int o = 16; o > 0; o >>= 1) {
            s += __shfl_down_sync(0xffffffffu, s, o);
            m = fmaxf(m, __shfl_down_sync(0xffffffffu, m, o));
        }
        if (lane == 0) {
            g_attn2[((size_t)b * NPOS + py * PP + px0 + px) * 2 + 0] = s * (1.f / DIM);
            g_attn2[((size_t)b * NPOS + py * PP + px0 + px) * 2 + 1] = m;
        }
    }
}

// ---------------- 2) q/k 3x3 convs (8 positions per block) -----------------
__global__ void qk_conv_kernel(const float* __restrict__ qw, const float* __restrict__ qb,
                               const float* __restrict__ kw, const float* __restrict__ kb) {
    int t = threadIdx.x;
    int p = blockIdx.x * 8 + (t >> 5), b = blockIdx.y;
    int tt = t & 31;
    int sel = tt >> 4, och = tt & 15;
    const float* w = sel ? kw : qw;
    const float* bi = sel ? kb : qb;
    float* outp = sel ? g_k : g_q;
    int py = p / PP, px = p % PP;
    float acc = bi[och];
#pragma unroll
    for (int dy = 0; dy < 3; dy++) {
        int iy = py - 1 + dy;
        if ((unsigned)iy >= PP) continue;
#pragma unroll
        for (int dx = 0; dx < 3; dx++) {
            int ix = px - 1 + dx;
            if ((unsigned)ix >= PP) continue;
            const float* a2 = &g_attn2[((size_t)b * NPOS + iy * PP + ix) * 2];
            acc += w[((och * 2 + 0) * 3 + dy) * 3 + dx] * a2[0]
                 + w[((och * 2 + 1) * 3 + dy) * 3 + dx] * a2[1];
        }
    }
    int h = och >> 1, comp = och & 1;
    outp[(((size_t)b * HEADS + h) * NPOS + p) * 2 + comp] = acc;
}

// ---------------- 3) depthwise 3x3 + BN + GELU (px-split, 2ch/thread) ------
__global__ void dw_part_kernel(const float* __restrict__ dww, const float* __restrict__ dwb,
                               const float* __restrict__ gamma, const float* __restrict__ beta,
                               const float* __restrict__ mean, const float* __restrict__ var) {
    int quarter = blockIdx.x, py = blockIdx.y, b = blockIdx.z, c2 = threadIdx.x;
    int c = 2 * c2;
    int px0 = quarter * 7;
    float2 wgt[9];
#pragma unroll
    for (int k = 0; k < 9; k++)
        wgt[k] = make_float2(dww[c * 9 + k], dww[(c + 1) * 9 + k]);
    float2 bias = *(const float2*)&dwb[c];
    float2 gmm = *(const float2*)&gamma[c];
    float2 vr2 = *(const float2*)&var[c];
    float2 sc = make_float2(gmm.x * rsqrtf(vr2.x + 1e-5f), gmm.y * rsqrtf(vr2.y + 1e-5f));
    float2 bm = *(const float2*)&mean[c];
    float2 bb = *(const float2*)&beta[c];

    const float* basep = g_xpool + (size_t)b * NPOS * DIM + c;
    float2 vin[3][9];
#pragma unroll
    for (int r = 0; r < 3; r++) {
        int row = py - 1 + r;
        bool vr = (unsigned)row < PP;
#pragma unroll
        for (int cc = 0; cc < 9; cc++) {
            int col = px0 - 1 + cc;
            vin[r][cc] = (vr && (unsigned)col < PP)
                       ? *(const float2*)&basep[(size_t)(row * PP + col) * DIM]
                       : make_float2(0.f, 0.f);
        }
    }
    __half* outp = g_vmid_h + ((size_t)b * NPOS + py * PP + px0) * DIM + c;
#pragma unroll
    for (int i = 0; i < 7; i++) {
        float ax = bias.x, ay = bias.y;
#pragma unroll
        for (int r = 0; r < 3; r++)
#pragma unroll
            for (int d = 0; d < 3; d++) {
                ax = fmaf(wgt[r * 3 + d].x, vin[r][i + d].x, ax);
                ay = fmaf(wgt[r * 3 + d].y, vin[r][i + d].y, ay);
            }
        ax = (ax - bm.x) * sc.x + bb.x;
        ay = (ay - bm.y) * sc.y + bb.y;
        ax = 0.5f * ax * (1.f + erff(ax * 0.70710678118654752f));
        ay = 0.5f * ay * (1.f + erff(ay * 0.70710678118654752f));
        *(uint32_t*)&outp[(size_t)i * DIM] = pack_h2(ax, ay);
    }
}

// ---------------- fp16 mma GEMM: C[M,N] = A[M,K]*B[N,K]^T + bias -----------
__global__ __launch_bounds__(256) void gemm_h_kernel(
        const __half* __restrict__ A, const __half* __restrict__ B,
        const float* __restrict__ bias, void* __restrict__ Cv,
        int M, int N, int K, int out_half) {
    __shared__ uint2 As2[2][2][128][4];
    __shared__ uint2 Bs2[2][2][128][4];
    int tid = threadIdx.x;
    int lane = tid & 31, w = tid >> 5, g = lane >> 2, tig = lane & 3;
    int wm = w >> 1, wn = w & 1;
    int m0 = blockIdx.y * 128, n0 = blockIdx.x * 128;
    float c[2][8][4] = {};

    int nchunks = K >> 5;
    int arow[2], aq[2];
#pragma unroll
    for (int i = 0; i < 2; i++) { int s = tid + i * 256; arow[i] = s >> 2; aq[i] = s & 3; }
    uint4 ra[2], rb[2];

#pragma unroll
    for (int i = 0; i < 2; i++) {
        ra[i] = *(const uint4*)&A[(size_t)(m0 + arow[i]) * K + aq[i] * 8];
        rb[i] = *(const uint4*)&B[(size_t)(n0 + arow[i]) * K + aq[i] * 8];
    }

#pragma unroll
    for (int i = 0; i < 2; i++) {
        uint32_t* pa = (uint32_t*)&As2[0][aq[i] >> 1][arow[i]][0] + (aq[i] & 1);
        pa[0] = ra[i].x; pa[2] = ra[i].y; pa[4] = ra[i].z; pa[6] = ra[i].w;
        uint32_t* pb = (uint32_t*)&Bs2[0][aq[i] >> 1][arow[i]][0] + (aq[i] & 1);
        pb[0] = rb[i].x; pb[2] = rb[i].y; pb[4] = rb[i].z; pb[6] = rb[i].w;
    }
    __syncthreads();

    for (int kc = 0; kc < nchunks; kc++) {
        int cur = kc & 1;
        if (kc + 1 < nchunks) {
            int ko = (kc + 1) * 32;
#pragma unroll
            for (int i = 0; i < 2; i++) {
                ra[i] = *(const uint4*)&A[(size_t)(m0 + arow[i]) * K + ko + aq[i] * 8];
                rb[i] = *(const uint4*)&B[(size_t)(n0 + arow[i]) * K + ko + aq[i] * 8];
            }
        }
#pragma unroll
        for (int kg = 0; kg < 2; kg++) {
            uint2 a00 = As2[cur][kg][wm * 32 + g][tig];
            uint2 a08 = As2[cur][kg][wm * 32 + 8 + g][tig];
            uint2 a16 = As2[cur][kg][wm * 32 + 16 + g][tig];
            uint2 a24 = As2[cur][kg][wm * 32 + 24 + g][tig];
#pragma unroll
            for (int nt = 0; nt < 8; nt++) {
                uint2 bb = Bs2[cur][kg][wn * 64 + nt * 8 + g][tig];
                mma_h(c[0][nt], a00.x, a08.x, a00.y, a08.y, bb.x, bb.y);
                mma_h(c[1][nt], a16.x, a24.x, a16.y, a24.y, bb.x, bb.y);
            }
        }
        if (kc + 1 < nchunks) {
            int nxt = cur ^ 1;
#pragma unroll
            for (int i = 0; i < 2; i++) {
                uint32_t* pa = (uint32_t*)&As2[nxt][aq[i] >> 1][arow[i]][0] + (aq[i] & 1);
                pa[0] = ra[i].x; pa[2] = ra[i].y; pa[4] = ra[i].z; pa[6] = ra[i].w;
                uint32_t* pb = (uint32_t*)&Bs2[nxt][aq[i] >> 1][arow[i]][0] + (aq[i] & 1);
                pb[0] = rb[i].x; pb[2] = rb[i].y; pb[4] = rb[i].z; pb[6] = rb[i].w;
            }
            __syncthreads();
        }
    }
#pragma unroll
    for (int mt = 0; mt < 2; mt++) {
        int r = m0 + wm * 32 + mt * 16 + g;
#pragma unroll
        for (int nt = 0; nt < 8; nt++) {
            int n = n0 + wn * 64 + nt * 8 + 2 * tig;
            float bx = bias[n], by = bias[n + 1];
            float o0 = c[mt][nt][0] + bx, o1 = c[mt][nt][1] + by;
            float o2 = c[mt][nt][2] + bx, o3 = c[mt][nt][3] + by;
            if (out_half) {
                __half* C = (__half*)Cv;
                *(uint32_t*)&C[(size_t)r * N + n] = pack_h2(o0, o1);
                *(uint32_t*)&C[(size_t)(r + 8) * N + n] = pack_h2(o2, o3);
            } else {
                float* C = (float*)Cv;
                *(float2*)&C[(size_t)r * N + n] = make_float2(o0, o1);
                *(float2*)&C[(size_t)(r + 8) * N + n] = make_float2(o2, o3);
            }
        }
    }
}

// ---------------- 5) attention per (b,h): fp16 mma + ldmatrix V ------------
// l accumulated in fp32 on the FMA pipe from the SAME packed fp16 p words fed
// to the MMA (replaces the ONES-mma: -1/9 tensor instructions, numerics same).
#define VROW 72
#define VTILE (16 * VROW)            // halves per jg tile (1152)
#define KXY_OFF (49 * VTILE * 2)     // 112896 bytes
#define ATTN_SMEM_SZ (KXY_OFF + NPOS * 8)   // +6272 = 119168

__global__ __launch_bounds__(800, 1) void attn_h_kernel() {
    extern __shared__ char smc[];
    __half* vtile = (__half*)smc;
    float2* kxy = (float2*)(smc + KXY_OFF);
    int h = blockIdx.x, b = blockIdx.y;
    int tid = threadIdx.x, lane = tid & 31, w = tid >> 5;
    int g = lane >> 2, tig = lane & 3;

    const __half* vsrc = g_v_h + (size_t)b * NPOS * INNER + h * DH;
    for (int i = tid; i < NPOS * 16; i += 800) {
        int j = i >> 4, q = i & 15;
        uint2 v = *(const uint2*)&vsrc[(size_t)j * INNER + q * 4];
        *(uint2*)&vtile[(j >> 4) * VTILE + (j & 15) * VROW + q * 4] = v;
    }
    const float* ksrc = g_k + ((size_t)b * HEADS + h) * NPOS * 2;
    const float KSC = 0.125f * 1.4426950408889634f;
    for (int i = tid; i < NPOS; i += 800) {
        float2 kv = ((const float2*)ksrc)[i];
        kxy[i] = make_float2(kv.x * KSC, kv.y * KSC);
    }
    __syncthreads();

    int mrow = (lane & 7) + ((lane >> 3) & 1) * 8;
    int nsub = (lane >> 4) * 8;
    uint32_t vbase = smem_u32(vtile) + (uint32_t)(mrow * VROW + nsub) * 2;

    const float2* qsrc = (const float2*)(g_q + ((size_t)b * HEADS + h) * NPOS * 2);
    __half* odst = g_ao_h + (size_t)b * NPOS * INNER + h * DH;

    for (int t = w; t < 49; t += 25) {
        int r0 = t * 16 + g, r1 = r0 + 8;
        float2 q0 = qsrc[r0], q1 = qsrc[r1];
        float c[8][4] = {};
        float l0 = 0.f, l1 = 0.f;   // row-sums for q0 (rows r0-frag) and q1
        for (int jg = 0; jg < 49; jg++) {
            float4 kk0 = *(const float4*)&kxy[jg * 16 + 2 * tig];
            float4 kk1 = *(const float4*)&kxy[jg * 16 + 2 * tig + 8];
            uint32_t a0 = exp2_h2(fmaf(q0.x, kk0.x, q0.y * kk0.y),
                                  fmaf(q0.x, kk0.z, q0.y * kk0.w));
            uint32_t a1 = exp2_h2(fmaf(q1.x, kk0.x, q1.y * kk0.y),
                                  fmaf(q1.x, kk0.z, q1.y * kk0.w));
            uint32_t a2 = exp2_h2(fmaf(q0.x, kk1.x, q0.y * kk1.y),
                                  fmaf(q0.x, kk1.z, q0.y * kk1.w));
            uint32_t a3 = exp2_h2(fmaf(q1.x, kk1.x, q1.y * kk1.y),
                                  fmaf(q1.x, kk1.z, q1.y * kk1.w));
            float2 f0 = __half22float2(*(__half2*)&a0);
            float2 f1 = __half22float2(*(__half2*)&a1);
            float2 f2 = __half22float2(*(__half2*)&a2);
            float2 f3 = __half22float2(*(__half2*)&a3);
            l0 += (f0.x + f0.y) + (f2.x + f2.y);
            l1 += (f1.x + f1.y) + (f3.x + f3.y);
            uint32_t vb = vbase + (uint32_t)jg * (VTILE * 2);
#pragma unroll
            for (int p = 0; p < 4; p++) {
                uint32_t r0r, r1r, r2r, r3r;
                asm volatile(
                    "ldmatrix.sync.aligned.m8n8.x4.trans.shared.b16 "
                    "{%0,%1,%2,%3}, [%4];"
                    : "=r"(r0r), "=r"(r1r), "=r"(r2r), "=r"(r3r)
                    : "r"(vb + (uint32_t)(p * 32)));
                mma_h(c[2 * p], a0, a1, a2, a3, r0r, r1r);
                mma_h(c[2 * p + 1], a0, a1, a2, a3, r2r, r3r);
            }
        }
        // reduce l across the 4 lanes of the quad (tig 0..3 cover all j)
        l0 += __shfl_xor_sync(0xffffffffu, l0, 1);
        l0 += __shfl_xor_sync(0xffffffffu, l0, 2);
        l1 += __shfl_xor_sync(0xffffffffu, l1, 1);
        l1 += __shfl_xor_sync(0xffffffffu, l1, 2);
        float i0 = 1.f / l0, i1 = 1.f / l1;
#pragma unroll
        for (int nt = 0; nt < 8; nt++) {
            int n = nt * 8 + 2 * tig;
            *(uint32_t*)&odst[(size_t)r0 * INNER + n] = pack_h2(c[nt][0] * i0, c[nt][1] * i0);
            *(uint32_t*)&odst[(size_t)r1 * INNER + n] = pack_h2(c[nt][2] * i1, c[nt][3] * i1);
        }
    }
}

// ---------------- 7) bicubic x2 upsample (reads fp16 y28) ------------------
__global__ void upsample3_kernel(float* __restrict__ out) {
    extern __shared__ float tmp[];   // [2][PP][DIM] dynamic (57344 B)
    float* tmp0 = tmp;
    float* tmp1 = tmp + PP * DIM;
    int m = blockIdx.x, b = blockIdx.y, c = threadIdx.x;
    int ry[5];
#pragma unroll
    for (int r = 0; r < 5; r++) ry[r] = min(max(m - 2 + r, 0), PP - 1);
    const __half* basep = g_y28_h + (size_t)b * NPOS * DIM + c;
#pragma unroll 7
    for (int ix = 0; ix < PP; ix++) {
        float v0 = __half2float(basep[(size_t)(ry[0] * PP + ix) * DIM]);
        float v1 = __half2float(basep[(size_t)(ry[1] * PP + ix) * DIM]);
        float v2 = __half2float(basep[(size_t)(ry[2] * PP + ix) * DIM]);
        float v3 = __half2float(basep[(size_t)(ry[3] * PP + ix) * DIM]);
        float v4 = __half2float(basep[(size_t)(ry[4] * PP + ix) * DIM]);
        tmp0[ix * DIM + c] = c_W75[0] * v0 + c_W75[1] * v1 + c_W75[2] * v2 + c_W75[3] * v3;
        tmp1[ix * DIM + c] = c_W25[0] * v1 + c_W25[1] * v2 + c_W25[2] * v3 + c_W25[3] * v4;
    }
    __syncthreads();
    float* orow0 = out + ((size_t)b * IMG * IMG + (2 * m) * IMG) * DIM + c;
    float* orow1 = orow0 + (size_t)IMG * DIM;
#pragma unroll 4
    for (int ox = 0; ox < IMG; ox++) {
        int ix0; const float* wx;
        if (ox & 1) { ix0 = (ox - 1) >> 1; wx = c_W25; }
        else        { ix0 = (ox >> 1) - 1; wx = c_W75; }
        int sx0 = min(max(ix0 - 1, 0), PP - 1);
        int sx1 = min(max(ix0 + 0, 0), PP - 1);
        int sx2 = min(max(ix0 + 1, 0), PP - 1);
        int sx3 = min(max(ix0 + 2, 0), PP - 1);
        float a0 = wx[0] * tmp0[sx0 * DIM + c] + wx[1] * tmp0[sx1 * DIM + c]
                 + wx[2] * tmp0[sx2 * DIM + c] + wx[3] * tmp0[sx3 * DIM + c];
        float a1 = wx[0] * tmp1[sx0 * DIM + c] + wx[1] * tmp1[sx1 * DIM + c]
                 + wx[2] * tmp1[sx2 * DIM + c] + wx[3] * tmp1[sx3 * DIM + c];
        orow0[(size_t)ox * DIM] = a0;
        orow1[(size_t)ox * DIM] = a1;
    }
}

// ---------------- launch ---------------------------------------------------
extern "C" void kernel_launch(void* const* d_in, const int* in_sizes, int n_in,
                              void* d_out, int out_size) {
    const float* x     = (const float*)d_in[0];
    const float* q_w   = (const float*)d_in[1];
    const float* q_b   = (const float*)d_in[2];
    const float* k_w   = (const float*)d_in[3];
    const float* k_b   = (const float*)d_in[4];
    const float* dw_w  = (const float*)d_in[5];
    const float* dw_b  = (const float*)d_in[6];
    const float* bn_g  = (const float*)d_in[7];
    const float* bn_b  = (const float*)d_in[8];
    const float* bn_m  = (const float*)d_in[9];
    const float* bn_v  = (const float*)d_in[10];
    const float* pw_w  = (const float*)d_in[11];
    const float* pw_b  = (const float*)d_in[12];
    const float* out_w = (const float*)d_in[13];
    const float* out_b = (const float*)d_in[14];
    float* out = (float*)d_out;

    const int UPS_SMEM = 2 * PP * DIM * (int)sizeof(float);   // 57344
    cudaFuncSetAttribute(attn_h_kernel, cudaFuncAttributeMaxDynamicSharedMemorySize, ATTN_SMEM_SZ);
    cudaFuncSetAttribute(upsample3_kernel, cudaFuncAttributeMaxDynamicSharedMemorySize, UPS_SMEM);

    void *p_vmid, *p_v, *p_ao, *p_y28, *p_pww, *p_oww;
    cudaGetSymbolAddress(&p_vmid, g_vmid_h);
    cudaGetSymbolAddress(&p_v, g_v_h);
    cudaGetSymbolAddress(&p_ao, g_ao_h);
    cudaGetSymbolAddress(&p_y28, g_y28_h);
    cudaGetSymbolAddress(&p_pww, g_pww_h);
    cudaGetSymbolAddress(&p_oww, g_oww_h);

    round_weights_kernel<<<(INNER * DIM + 255) / 256, 256>>>(pw_w, out_w);
    pool_part_kernel<<<dim3(4, PP, BATCH), 128>>>(x);
    qk_conv_kernel<<<dim3(NPOS / 8, BATCH), 256>>>(q_w, q_b, k_w, k_b);
    dw_part_kernel<<<dim3(4, PP, BATCH), 128>>>(dw_w, dw_b, bn_g, bn_b, bn_m, bn_v);
    // pointwise conv: [12544,256] x [512,256]^T -> fp16 [12544,512]
    gemm_h_kernel<<<dim3(INNER / 128, (BATCH * NPOS) / 128), 256>>>(
        (const __half*)p_vmid, (const __half*)p_pww, pw_b, p_v,
        BATCH * NPOS, INNER, DIM, 1);
    attn_h_kernel<<<dim3(HEADS, BATCH), 800, ATTN_SMEM_SZ>>>();
    // output projection: [12544,512] x [256,512]^T -> fp16 [12544,256]
    gemm_h_kernel<<<dim3(DIM / 128, (BATCH * NPOS) / 128), 256>>>(
        (const __half*)p_ao, (const __half*)p_oww, out_b, p_y28,
        BATCH * NPOS, DIM, INNER, 1);
    upsample3_kernel<<<dim3(PP, BATCH), 256, UPS_SMEM>>>(out);
}

// round 16
// speedup vs baseline: 1.0248x; 1.0248x over previous
#include <cuda_runtime.h>
#include <cuda_fp16.h>
#include <math.h>
#include <stdint.h>

#define BATCH 16
#define IMG 56
#define PP 28
#define NPOS 784
#define DIM 256
#define HEADS 8
#define DH 64
#define INNER 512

// ---------------- scratch (static device allocations; no cudaMalloc) -------
__device__ float  g_xpool[BATCH * NPOS * DIM];
__device__ float  g_attn2[BATCH * NPOS * 2];
__device__ float  g_q[BATCH * HEADS * NPOS * 2];
__device__ float  g_k[BATCH * HEADS * NPOS * 2];
__device__ __half g_vmid_h[BATCH * NPOS * DIM];
__device__ __half g_v_h[BATCH * NPOS * INNER];
__device__ __half g_ao_h[BATCH * NPOS * INNER];
__device__ __half g_y28_h[BATCH * NPOS * DIM];   // out-proj result (fp16)
__device__ __half g_pww_h[INNER * DIM];
__device__ __half g_oww_h[DIM * INNER];

__constant__ float c_W25[4] = {-0.10546875f, 0.87890625f, 0.26171875f, -0.03515625f};
__constant__ float c_W75[4] = {-0.03515625f, 0.26171875f, 0.87890625f, -0.10546875f};

// ---------------- helpers ---------------------------------------------------
__device__ __forceinline__ uint32_t pack_h2(float lo, float hi) {
    uint32_t r;
    asm("cvt.rn.f16x2.f32 %0, %1, %2;" : "=r"(r) : "f"(hi), "f"(lo));
    return r;
}
__device__ __forceinline__ uint32_t exp2_h2(float lo, float hi) {
    uint32_t s = pack_h2(lo, hi);
    uint32_t r;
    asm("ex2.approx.f16x2 %0, %1;" : "=r"(r) : "r"(s));
    return r;
}
__device__ __forceinline__ void mma_h(float c[4], uint32_t a0, uint32_t a1,
                                      uint32_t a2, uint32_t a3,
                                      uint32_t b0, uint32_t b1) {
    asm volatile(
        "mma.sync.aligned.m16n8k16.row.col.f32.f16.f16.f32 "
        "{%0,%1,%2,%3},{%4,%5,%6,%7},{%8,%9},{%0,%1,%2,%3};"
        : "+f"(c[0]), "+f"(c[1]), "+f"(c[2]), "+f"(c[3])
        : "r"(a0), "r"(a1), "r"(a2), "r"(a3), "r"(b0), "r"(b1));
}
__device__ __forceinline__ uint32_t smem_u32(const void* p) {
    uint32_t a;
    asm("{ .reg .u64 t; cvta.to.shared.u64 t, %1; cvt.u32.u64 %0, t; }" : "=r"(a) : "l"(p));
    return a;
}

// ---------------- 1) avgpool + stats (px-split, 2ch) + weight convert ------
// grid (5, PP, BATCH), 128 threads. quarter<4: pool; quarter==4: fp16 weights.
__global__ void pool_part_kernel(const float* __restrict__ x,
                                 const float* __restrict__ pw,
                                 const float* __restrict__ ow) {
    __shared__ float srow[7][DIM];
    int quarter = blockIdx.x, py = blockIdx.y, b = blockIdx.z;
    int c2 = threadIdx.x, c = 2 * c2;
    if (quarter == 4) {
        int idx0 = (b * PP + py) * 128 + c2;
        for (int i = idx0; i < INNER * DIM; i += PP * BATCH * 128) {
            g_pww_h[i] = __float2half(pw[i]);
            g_oww_h[i] = __float2half(ow[i]);
        }
        return;
    }
    int lane = c2 & 31, w4 = c2 >> 5;
    int px0 = quarter * 7;
    const float* base = x + (size_t)b * IMG * IMG * DIM + c;
    int rm = 2 * py - 1, r0 = 2 * py, rp = 2 * py + 1;
    bool vm = rm >= 0;

    float2 cs[15];
#pragma unroll
    for (int i = 0; i < 15; i++) {
        int ix = 2 * px0 - 1 + i;
        if ((unsigned)ix < IMG) {
            float2 a = *(const float2*)&base[(size_t)(r0 * IMG + ix) * DIM];
            float2 bq = *(const float2*)&base[(size_t)(rp * IMG + ix) * DIM];
            float2 v = make_float2(a.x + bq.x, a.y + bq.y);
            if (vm) {
                float2 m2 = *(const float2*)&base[(size_t)(rm * IMG + ix) * DIM];
                v.x += m2.x; v.y += m2.y;
            }
            cs[i] = v;
        } else cs[i] = make_float2(0.f, 0.f);
    }
    float* outp = g_xpool + ((size_t)b * NPOS + py * PP + px0) * DIM + c;
#pragma unroll
    for (int i = 0; i < 7; i++) {
        float2 pool;
        pool.x = (cs[2 * i].x + cs[2 * i + 1].x + cs[2 * i + 2].x) * (1.f / 9.f);
        pool.y = (cs[2 * i].y + cs[2 * i + 1].y + cs[2 * i + 2].y) * (1.f / 9.f);
        *(float2*)&outp[(size_t)i * DIM] = pool;
        *(float2*)&srow[i][c] = pool;
    }
    __syncthreads();
    for (int px = w4; px < 7; px += 4) {
        float s = 0.f, m = -1e30f;
#pragma unroll
        for (int k = 0; k < 8; k++) {
            float v = srow[px][lane + 32 * k];
            s += v; m = fmaxf(m, v);
        }
#pragma unroll
        for (int o = 16; o > 0; o >>= 1) {
            s += __shfl_down_sync(0xffffffffu, s, o);
            m = fmaxf(m, __shfl_down_sync(0xffffffffu, m, o));
        }
        if (lane == 0) {
            g_attn2[((size_t)b * NPOS + py * PP + px0 + px) * 2 + 0] = s * (1.f / DIM);
            g_attn2[((size_t)b * NPOS + py * PP + px0 + px) * 2 + 1] = m;
        }
    }
}

// ---------------- 3) depthwise+BN+GELU (px-split, 2ch) + qk conv -----------
// grid (5, PP, BATCH), 128 threads. quarter<4: dw; quarter==4: q/k 3x3 conv.
__global__ void dw_part_kernel(const float* __restrict__ dww, const float* __restrict__ dwb,
                               const float* __restrict__ gamma, const float* __restrict__ beta,
                               const float* __restrict__ mean, const float* __restrict__ var,
                               const float* __restrict__ qw, const float* __restrict__ qb,
                               const float* __restrict__ kw, const float* __restrict__ kb) {
    int quarter = blockIdx.x, py = blockIdx.y, b = blockIdx.z, c2 = threadIdx.x;
    if (quarter == 4) {
        // q/k conv: this block covers 28 positions (p = py*28 + 0..27) x 32 (sel,och)
        for (int wk = c2; wk < PP * 32; wk += 128) {
            int pl = wk >> 5, tt = wk & 31;
            int p = py * PP + pl;
            int sel = tt >> 4, och = tt & 15;
            const float* w = sel ? kw : qw;
            const float* bi = sel ? kb : qb;
            float* outp = sel ? g_k : g_q;
            int ppy = p / PP, ppx = p % PP;
            float acc = bi[och];
#pragma unroll
            for (int dy = 0; dy < 3; dy++) {
                int iy = ppy - 1 + dy;
                if ((unsigned)iy >= PP) continue;
#pragma unroll
                for (int dx = 0; dx < 3; dx++) {
                    int ix = ppx - 1 + dx;
                    if ((unsigned)ix >= PP) continue;
                    const float* a2 = &g_attn2[((size_t)b * NPOS + iy * PP + ix) * 2];
                    acc += w[((och * 2 + 0) * 3 + dy) * 3 + dx] * a2[0]
                         + w[((och * 2 + 1) * 3 + dy) * 3 + dx] * a2[1];
                }
            }
            int h = och >> 1, comp = och & 1;
            outp[(((size_t)b * HEADS + h) * NPOS + p) * 2 + comp] = acc;
        }
        return;
    }
    int c = 2 * c2;
    int px0 = quarter * 7;
    float2 wgt[9];
#pragma unroll
    for (int k = 0; k < 9; k++)
        wgt[k] = make_float2(dww[c * 9 + k], dww[(c + 1) * 9 + k]);
    float2 bias = *(const float2*)&dwb[c];
    float2 gmm = *(const float2*)&gamma[c];
    float2 vr2 = *(const float2*)&var[c];
    float2 sc = make_float2(gmm.x * rsqrtf(vr2.x + 1e-5f), gmm.y * rsqrtf(vr2.y + 1e-5f));
    float2 bm = *(const float2*)&mean[c];
    float2 bb = *(const float2*)&beta[c];

    const float* basep = g_xpool + (size_t)b * NPOS * DIM + c;
    float2 vin[3][9];
#pragma unroll
    for (int r = 0; r < 3; r++) {
        int row = py - 1 + r;
        bool vr = (unsigned)row < PP;
#pragma unroll
        for (int cc = 0; cc < 9; cc++) {
            int col = px0 - 1 + cc;
            vin[r][cc] = (vr && (unsigned)col < PP)
                       ? *(const float2*)&basep[(size_t)(row * PP + col) * DIM]
                       : make_float2(0.f, 0.f);
        }
    }
    __half* outp = g_vmid_h + ((size_t)b * NPOS + py * PP + px0) * DIM + c;
#pragma unroll
    for (int i = 0; i < 7; i++) {
        float ax = bias.x, ay = bias.y;
#pragma unroll
        for (int r = 0; r < 3; r++)
#pragma unroll
            for (int d = 0; d < 3; d++) {
                ax = fmaf(wgt[r * 3 + d].x, vin[r][i + d].x, ax);
                ay = fmaf(wgt[r * 3 + d].y, vin[r][i + d].y, ay);
            }
        ax = (ax - bm.x) * sc.x + bb.x;
        ay = (ay - bm.y) * sc.y + bb.y;
        ax = 0.5f * ax * (1.f + erff(ax * 0.70710678118654752f));
        ay = 0.5f * ay * (1.f + erff(ay * 0.70710678118654752f));
        *(uint32_t*)&outp[(size_t)i * DIM] = pack_h2(ax, ay);
    }
}

// ---------------- fp16 mma GEMM: C[M,N] = A[M,K]*B[N,K]^T + bias -----------
__global__ __launch_bounds__(256) void gemm_h_kernel(
        const __half* __restrict__ A, const __half* __restrict__ B,
        const float* __restrict__ bias, void* __restrict__ Cv,
        int M, int N, int K, int out_half) {
    __shared__ uint2 As2[2][2][128][4];
    __shared__ uint2 Bs2[2][2][128][4];
    int tid = threadIdx.x;
    int lane = tid & 31, w = tid >> 5, g = lane >> 2, tig = lane & 3;
    int wm = w >> 1, wn = w & 1;
    int m0 = blockIdx.y * 128, n0 = blockIdx.x * 128;
    float c[2][8][4] = {};

    int nchunks = K >> 5;
    int arow[2], aq[2];
#pragma unroll
    for (int i = 0; i < 2; i++) { int s = tid + i * 256; arow[i] = s >> 2; aq[i] = s & 3; }
    uint4 ra[2], rb[2];

#pragma unroll
    for (int i = 0; i < 2; i++) {
        ra[i] = *(const uint4*)&A[(size_t)(m0 + arow[i]) * K + aq[i] * 8];
        rb[i] = *(const uint4*)&B[(size_t)(n0 + arow[i]) * K + aq[i] * 8];
    }

#pragma unroll
    for (int i = 0; i < 2; i++) {
        uint32_t* pa = (uint32_t*)&As2[0][aq[i] >> 1][arow[i]][0] + (aq[i] & 1);
        pa[0] = ra[i].x; pa[2] = ra[i].y; pa[4] = ra[i].z; pa[6] = ra[i].w;
        uint32_t* pb = (uint32_t*)&Bs2[0][aq[i] >> 1][arow[i]][0] + (aq[i] & 1);
        pb[0] = rb[i].x; pb[2] = rb[i].y; pb[4] = rb[i].z; pb[6] = rb[i].w;
    }
    __syncthreads();

    for (int kc = 0; kc < nchunks; kc++) {
        int cur = kc & 1;
        if (kc + 1 < nchunks) {
            int ko = (kc + 1) * 32;
#pragma unroll
            for (int i = 0; i < 2; i++) {
                ra[i] = *(const uint4*)&A[(size_t)(m0 + arow[i]) * K + ko + aq[i] * 8];
                rb[i] = *(const uint4*)&B[(size_t)(n0 + arow[i]) * K + ko + aq[i] * 8];
            }
        }
#pragma unroll
        for (int kg = 0; kg < 2; kg++) {
            uint2 a00 = As2[cur][kg][wm * 32 + g][tig];
            uint2 a08 = As2[cur][kg][wm * 32 + 8 + g][tig];
            uint2 a16 = As2[cur][kg][wm * 32 + 16 + g][tig];
            uint2 a24 = As2[cur][kg][wm * 32 + 24 + g][tig];
#pragma unroll
            for (int nt = 0; nt < 8; nt++) {
                uint2 bb = Bs2[cur][kg][wn * 64 + nt * 8 + g][tig];
                mma_h(c[0][nt], a00.x, a08.x, a00.y, a08.y, bb.x, bb.y);
                mma_h(c[1][nt], a16.x, a24.x, a16.y, a24.y, bb.x, bb.y);
            }
        }
        if (kc + 1 < nchunks) {
            int nxt = cur ^ 1;
#pragma unroll
            for (int i = 0; i < 2; i++) {
                uint32_t* pa = (uint32_t*)&As2[nxt][aq[i] >> 1][arow[i]][0] + (aq[i] & 1);
                pa[0] = ra[i].x; pa[2] = ra[i].y; pa[4] = ra[i].z; pa[6] = ra[i].w;
                uint32_t* pb = (uint32_t*)&Bs2[nxt][aq[i] >> 1][arow[i]][0] + (aq[i] & 1);
                pb[0] = rb[i].x; pb[2] = rb[i].y; pb[4] = rb[i].z; pb[6] = rb[i].w;
            }
            __syncthreads();
        }
    }
#pragma unroll
    for (int mt = 0; mt < 2; mt++) {
        int r = m0 + wm * 32 + mt * 16 + g;
#pragma unroll
        for (int nt = 0; nt < 8; nt++) {
            int n = n0 + wn * 64 + nt * 8 + 2 * tig;
            float bx = bias[n], by = bias[n + 1];
            float o0 = c[mt][nt][0] + bx, o1 = c[mt][nt][1] + by;
            float o2 = c[mt][nt][2] + bx, o3 = c[mt][nt][3] + by;
            if (out_half) {
                __half* C = (__half*)Cv;
                *(uint32_t*)&C[(size_t)r * N + n] = pack_h2(o0, o1);
                *(uint32_t*)&C[(size_t)(r + 8) * N + n] = pack_h2(o2, o3);
            } else {
                float* C = (float*)Cv;
                *(float2*)&C[(size_t)r * N + n] = make_float2(o0, o1);
                *(float2*)&C[(size_t)(r + 8) * N + n] = make_float2(o2, o3);
            }
        }
    }
}

// ---------------- 5) attention per (b,h): R14 best (ONES-mma + ldmatrix) ---
#define VROW 72
#define VTILE (16 * VROW)            // halves per jg tile (1152)
#define KXY_OFF (49 * VTILE * 2)     // 112896 bytes
#define ATTN_SMEM_SZ (KXY_OFF + NPOS * 8)   // +6272 = 119168

__global__ __launch_bounds__(800, 1) void attn_h_kernel() {
    extern __shared__ char smc[];
    __half* vtile = (__half*)smc;
    float2* kxy = (float2*)(smc + KXY_OFF);
    int h = blockIdx.x, b = blockIdx.y;
    int tid = threadIdx.x, lane = tid & 31, w = tid >> 5;
    int g = lane >> 2, tig = lane & 3;
    const uint32_t ONES = 0x3C003C00u;

    const __half* vsrc = g_v_h + (size_t)b * NPOS * INNER + h * DH;
    for (int i = tid; i < NPOS * 16; i += 800) {
        int j = i >> 4, q = i & 15;
        uint2 v = *(const uint2*)&vsrc[(size_t)j * INNER + q * 4];
        *(uint2*)&vtile[(j >> 4) * VTILE + (j & 15) * VROW + q * 4] = v;
    }
    const float* ksrc = g_k + ((size_t)b * HEADS + h) * NPOS * 2;
    const float KSC = 0.125f * 1.4426950408889634f;
    for (int i = tid; i < NPOS; i += 800) {
        float2 kv = ((const float2*)ksrc)[i];
        kxy[i] = make_float2(kv.x * KSC, kv.y * KSC);
    }
    __syncthreads();

    int mrow = (lane & 7) + ((lane >> 3) & 1) * 8;
    int nsub = (lane >> 4) * 8;
    uint32_t vbase = smem_u32(vtile) + (uint32_t)(mrow * VROW + nsub) * 2;

    const float2* qsrc = (const float2*)(g_q + ((size_t)b * HEADS + h) * NPOS * 2);
    __half* odst = g_ao_h + (size_t)b * NPOS * INNER + h * DH;

    for (int t = w; t < 49; t += 25) {
        int r0 = t * 16 + g, r1 = r0 + 8;
        float2 q0 = qsrc[r0], q1 = qsrc[r1];
        float c[8][4] = {};
        float cl[4] = {};
        for (int jg = 0; jg < 49; jg++) {
            float4 kk0 = *(const float4*)&kxy[jg * 16 + 2 * tig];
            float4 kk1 = *(const float4*)&kxy[jg * 16 + 2 * tig + 8];
            uint32_t a0 = exp2_h2(fmaf(q0.x, kk0.x, q0.y * kk0.y),
                                  fmaf(q0.x, kk0.z, q0.y * kk0.w));
            uint32_t a1 = exp2_h2(fmaf(q1.x, kk0.x, q1.y * kk0.y),
                                  fmaf(q1.x, kk0.z, q1.y * kk0.w));
            uint32_t a2 = exp2_h2(fmaf(q0.x, kk1.x, q0.y * kk1.y),
                                  fmaf(q0.x, kk1.z, q0.y * kk1.w));
            uint32_t a3 = exp2_h2(fmaf(q1.x, kk1.x, q1.y * kk1.y),
                                  fmaf(q1.x, kk1.z, q1.y * kk1.w));
            uint32_t vb = vbase + (uint32_t)jg * (VTILE * 2);
#pragma unroll
            for (int p = 0; p < 4; p++) {
                uint32_t r0r, r1r, r2r, r3r;
                asm volatile(
                    "ldmatrix.sync.aligned.m8n8.x4.trans.shared.b16 "
                    "{%0,%1,%2,%3}, [%4];"
                    : "=r"(r0r), "=r"(r1r), "=r"(r2r), "=r"(r3r)
                    : "r"(vb + (uint32_t)(p * 32)));
                mma_h(c[2 * p], a0, a1, a2, a3, r0r, r1r);
                mma_h(c[2 * p + 1], a0, a1, a2, a3, r2r, r3r);
            }
            mma_h(cl, a0, a1, a2, a3, ONES, ONES);
        }
        float i0 = 1.f / cl[0], i1 = 1.f / cl[2];
#pragma unroll
        for (int nt = 0; nt < 8; nt++) {
            int n = nt * 8 + 2 * tig;
            *(uint32_t*)&odst[(size_t)r0 * INNER + n] = pack_h2(c[nt][0] * i0, c[nt][1] * i0);
            *(uint32_t*)&odst[(size_t)r1 * INNER + n] = pack_h2(c[nt][2] * i1, c[nt][3] * i1);
        }
    }
}

// ---------------- 7) bicubic x2 upsample (reads fp16 y28) ------------------
__global__ void upsample3_kernel(float* __restrict__ out) {
    extern __shared__ float tmp[];   // [2][PP][DIM] dynamic (57344 B)
    float* tmp0 = tmp;
    float* tmp1 = tmp + PP * DIM;
    int m = blockIdx.x, b = blockIdx.y, c = threadIdx.x;
    int ry[5];
#pragma unroll
    for (int r = 0; r < 5; r++) ry[r] = min(max(m - 2 + r, 0), PP - 1);
    const __half* basep = g_y28_h + (size_t)b * NPOS * DIM + c;
#pragma unroll 7
    for (int ix = 0; ix < PP; ix++) {
        float v0 = __half2float(basep[(size_t)(ry[0] * PP + ix) * DIM]);
        float v1 = __half2float(basep[(size_t)(ry[1] * PP + ix) * DIM]);
        float v2 = __half2float(basep[(size_t)(ry[2] * PP + ix) * DIM]);
        float v3 = __half2float(basep[(size_t)(ry[3] * PP + ix) * DIM]);
        float v4 = __half2float(basep[(size_t)(ry[4] * PP + ix) * DIM]);
        tmp0[ix * DIM + c] = c_W75[0] * v0 + c_W75[1] * v1 + c_W75[2] * v2 + c_W75[3] * v3;
        tmp1[ix * DIM + c] = c_W25[0] * v1 + c_W25[1] * v2 + c_W25[2] * v3 + c_W25[3] * v4;
    }
    __syncthreads();
    float* orow0 = out + ((size_t)b * IMG * IMG + (2 * m) * IMG) * DIM + c;
    float* orow1 = orow0 + (size_t)IMG * DIM;
#pragma unroll 4
    for (int ox = 0; ox < IMG; ox++) {
        int ix0; const float* wx;
        if (ox & 1) { ix0 = (ox - 1) >> 1; wx = c_W25; }
        else        { ix0 = (ox >> 1) - 1; wx = c_W75; }
        int sx0 = min(max(ix0 - 1, 0), PP - 1);
        int sx1 = min(max(ix0 + 0, 0), PP - 1);
        int sx2 = min(max(ix0 + 1, 0), PP - 1);
        int sx3 = min(max(ix0 + 2, 0), PP - 1);
        float a0 = wx[0] * tmp0[sx0 * DIM + c] + wx[1] * tmp0[sx1 * DIM + c]
                 + wx[2] * tmp0[sx2 * DIM + c] + wx[3] * tmp0[sx3 * DIM + c];
        float a1 = wx[0] * tmp1[sx0 * DIM + c] + wx[1] * tmp1[sx1 * DIM + c]
                 + wx[2] * tmp1[sx2 * DIM + c] + wx[3] * tmp1[sx3 * DIM + c];
        orow0[(size_t)ox * DIM] = a0;
        orow1[(size_t)ox * DIM] = a1;
    }
}

// ---------------- launch ---------------------------------------------------
extern "C" void kernel_launch(void* const* d_in, const int* in_sizes, int n_in,
                              void* d_out, int out_size) {
    const float* x     = (const float*)d_in[0];
    const float* q_w   = (const float*)d_in[1];
    const float* q_b   = (const float*)d_in[2];
    const float* k_w   = (const float*)d_in[3];
    const float* k_b   = (const float*)d_in[4];
    const float* dw_w  = (const float*)d_in[5];
    const float* dw_b  = (const float*)d_in[6];
    const float* bn_g  = (const float*)d_in[7];
    const float* bn_b  = (const float*)d_in[8];
    const float* bn_m  = (const float*)d_in[9];
    const float* bn_v  = (const float*)d_in[10];
    const float* pw_w  = (const float*)d_in[11];
    const float* pw_b  = (const float*)d_in[12];
    const float* out_w = (const float*)d_in[13];
    const float* out_b = (const float*)d_in[14];
    float* out = (float*)d_out;

    const int UPS_SMEM = 2 * PP * DIM * (int)sizeof(float);   // 57344
    cudaFuncSetAttribute(attn_h_kernel, cudaFuncAttributeMaxDynamicSharedMemorySize, ATTN_SMEM_SZ);
    cudaFuncSetAttribute(upsample3_kernel, cudaFuncAttributeMaxDynamicSharedMemorySize, UPS_SMEM);

    void *p_vmid, *p_v, *p_ao, *p_y28, *p_pww, *p_oww;
    cudaGetSymbolAddress(&p_vmid, g_vmid_h);
    cudaGetSymbolAddress(&p_v, g_v_h);
    cudaGetSymbolAddress(&p_ao, g_ao_h);
    cudaGetSymbolAddress(&p_y28, g_y28_h);
    cudaGetSymbolAddress(&p_pww, g_pww_h);
    cudaGetSymbolAddress(&p_oww, g_oww_h);

    // pool + weight-convert fused (quarter 4 = weights)
    pool_part_kernel<<<dim3(5, PP, BATCH), 128>>>(x, pw_w, out_w);
    // dw + qk conv fused (quarter 4 = qk)
    dw_part_kernel<<<dim3(5, PP, BATCH), 128>>>(dw_w, dw_b, bn_g, bn_b, bn_m, bn_v,
                                                q_w, q_b, k_w, k_b);
    // pointwise conv: [12544,256] x [512,256]^T -> fp16 [12544,512]
    gemm_h_kernel<<<dim3(INNER / 128, (BATCH * NPOS) / 128), 256>>>(
        (const __half*)p_vmid, (const __half*)p_pww, pw_b, p_v,
        BATCH * NPOS, INNER, DIM, 1);
    attn_h_kernel<<<dim3(HEADS, BATCH), 800, ATTN_SMEM_SZ>>>();
    // output projection: [12544,512] x [256,512]^T -> fp16 [12544,256]
    gemm_h_kernel<<<dim3(DIM / 128, (BATCH * NPOS) / 128), 256>>>(
        (const __half*)p_ao, (const __half*)p_oww, out_b, p_y28,
        BATCH * NPOS, DIM, INNER, 1);
    upsample3_kernel<<<dim3(PP, BATCH), 256, UPS_SMEM>>>(out);
}